// round 17
// baseline (speedup 1.0000x reference)
#include <cuda_runtime.h>
#include <math.h>

#define NLAYERS 4
#define HID 64
#define NROWS 8192            // B*N = 2*4096
#define NPB   4096.0f
#define TROWS 32              // rows per consumer CTA tile
#define NAPPLY 256            // 8192 / 32 apply CTAs
#define NPROD  16             // producer (tiny) CTAs
#define HTS 36                // ht[j][r] stride
#define HSS 68                // hs[r][l] stride

// Accumulator block (zeroed each replay): S, sv, done-flags
#define ACC_S    0                                  // 8 * 4096
#define ACC_SV   (NLAYERS * 2 * HID * HID)          // 32768, 8*64
#define ACC_DONE (ACC_SV + NLAYERS * 2 * HID)       // 33280, 8 slots
#define ACC_TOT  (ACC_DONE + 8)                     // 33288

__device__ float g_acc[ACC_TOT];
__device__ float g_h[NROWS * HID];
__device__ float g_Weff[2 * HID * HID];
__device__ float g_beff[2 * HID];

__device__ __forceinline__ float gelu_exact(float x) {
    return 0.5f * x * (1.0f + erff(x * 0.70710678118654752440f));
}

__device__ __forceinline__ void red_v4(float* p, float a, float b, float c, float d) {
    asm volatile("red.global.add.v4.f32 [%0], {%1,%2,%3,%4};"
                 :: "l"(p), "f"(a), "f"(b), "f"(c), "f"(d) : "memory");
}

// ---------------------------------------------------------------------------
// S-phase (256 threads, 32-row tile): S += hs^T hs, sv += colsum(hs).
// ---------------------------------------------------------------------------
__device__ __forceinline__ void accum_S(const float* hs, float* Sdst, float* svdst, int tid)
{
    int txl = tid & 15, tyj = tid >> 4;
    float macc[4][4];
    #pragma unroll
    for (int a = 0; a < 4; a++)
        #pragma unroll
        for (int b = 0; b < 4; b++) macc[a][b] = 0.0f;

    const float* pj = hs + 4 * tyj;
    const float* pl = hs + 4 * txl;
    #pragma unroll 8
    for (int r = 0; r < TROWS; r++) {
        float4 aj = *(const float4*)(pj + r * HSS);
        float4 bl = *(const float4*)(pl + r * HSS);
        float av[4] = {aj.x, aj.y, aj.z, aj.w};
        float bv[4] = {bl.x, bl.y, bl.z, bl.w};
        #pragma unroll
        for (int a = 0; a < 4; a++)
            #pragma unroll
            for (int b = 0; b < 4; b++)
                macc[a][b] = fmaf(av[a], bv[b], macc[a][b]);
    }
    #pragma unroll
    for (int a = 0; a < 4; a++)
        red_v4(Sdst + (4 * tyj + a) * HID + 4 * txl,
               macc[a][0], macc[a][1], macc[a][2], macc[a][3]);

    if (tid < 64) {
        float s = 0.0f;
        #pragma unroll 8
        for (int r = 0; r < TROWS; r++) s += hs[r * HSS + tid];
        atomicAdd(&svdst[tid], s);
    }
}

// ---------------------------------------------------------------------------
__global__ __launch_bounds__(256) void zero_kernel()
{
    int idx = blockIdx.x * 256 + threadIdx.x;
    if (idx < ACC_TOT) g_acc[idx] = 0.0f;
}

// ---------------------------------------------------------------------------
// lift_S: h = x @ lift_w + lift_b; write g_h; accumulate S0, s0. grid 256x256.
// ---------------------------------------------------------------------------
__global__ __launch_bounds__(256) void lift_S_kernel(
    const float* __restrict__ x, const float* __restrict__ lw,
    const float* __restrict__ lb)
{
    __shared__ float hs[TROWS * HSS];
    int tid = threadIdx.x;
    int r0  = blockIdx.x * TROWS;
    int batch = r0 >> 12;

    #pragma unroll
    for (int it = 0; it < 8; it++) {
        int idx = tid + 256 * it;              // 2048 elements
        int r = idx >> 6, c = idx & 63;
        const float* xr = x + (r0 + r) * 3;
        float acc = lb[c];
        acc = fmaf(xr[0], lw[c],        acc);
        acc = fmaf(xr[1], lw[64 + c],   acc);
        acc = fmaf(xr[2], lw[128 + c],  acc);
        g_h[(r0 + r) * HID + c] = acc;
        hs[r * HSS + c] = acc;
    }
    __syncthreads();
    accum_S(hs, g_acc + ACC_S + batch * (HID * HID),
            g_acc + ACC_SV + batch * HID, tid);
}

// ---------------------------------------------------------------------------
// tiny (producer CTAs 0..15 of the fused kernel): compute W_eff / b_eff.
// ---------------------------------------------------------------------------
__device__ void tiny_phase(float* smT, int layer, int cta,
    const float* qw, const float* qb, const float* kw, const float* kb,
    const float* vw, const float* vb, const float* bw, const float* bb)
{
    float* sS   = smT;               // [64][65]
    float* sWk  = sS  + 64 * 65;
    float* sWq  = sWk + 64 * 65;
    float* sWv8 = sWq + 64 * 65;     // [64][8]
    float* sA   = sWv8 + 64 * 8;     // [64][9]
    float* sM   = sA  + 64 * 9;      // [64][9]
    float* ssum = sM  + 64 * 9;      // [64]
    float* swv  = ssum + 64;         // [64]
    float* su   = swv + 64;          // [8]

    int tid = threadIdx.x;
    int b   = cta >> 3;
    int cc  = cta & 7;
    int l0  = 8 * cc;

    const float* Sg = g_acc + ACC_S + (layer & 1 ? 0 : 0) + (layer * 2 + b) * (HID * HID);
    const float* sv = g_acc + ACC_SV + (layer * 2 + b) * HID;

    #pragma unroll
    for (int it = 0; it < 16; it++) {
        int f = tid + 256 * it;
        int rr = f >> 6, mm = f & 63;
        sS [rr * 65 + mm] = Sg[f];
        sWk[rr * 65 + mm] = kw[f];
        sWq[rr * 65 + mm] = qw[f];
    }
    if (tid < 128) {
        int m = tid >> 1, hf = tid & 1;
        float4 v = *(const float4*)(vw + m * 64 + l0 + 4 * hf);
        *(float4*)(sWv8 + m * 8 + 4 * hf) = v;
    }
    if (tid < 64) ssum[tid] = sv[tid];
    __syncthreads();

    int j = tid & 63, g = tid >> 6;
    int ll = 2 * g;
    int la = l0 + ll;

    if (g == 0) {
        float acc = 0.0f;
        #pragma unroll 8
        for (int m = 0; m < 64; m++) acc = fmaf(sWk[m * 65 + j], ssum[m], acc);
        swv[j] = acc;
    } else if (g == 1 && j < 8) {
        float acc = 0.0f;
        #pragma unroll 8
        for (int m = 0; m < 64; m++) acc = fmaf(ssum[m], sWv8[m * 8 + j], acc);
        su[j] = acc;
    }

    {
        float a0 = 0.0f, a1 = 0.0f;
        #pragma unroll 8
        for (int m = 0; m < 64; m++) {
            float s = sS[j * 65 + m];
            a0 = fmaf(s, sWv8[m * 8 + ll],     a0);
            a1 = fmaf(s, sWv8[m * 8 + ll + 1], a1);
        }
        sA[j * 9 + ll]     = a0;
        sA[j * 9 + ll + 1] = a1;
    }
    __syncthreads();

    {
        float bkj = kb[j];
        float bv0 = vb[la], bv1 = vb[la + 1];
        float m0 = fmaf(swv[j], bv0, bkj * (su[ll]     + NPB * bv0));
        float m1 = fmaf(swv[j], bv1, bkj * (su[ll + 1] + NPB * bv1));
        #pragma unroll 8
        for (int m = 0; m < 64; m++) {
            float wk = sWk[m * 65 + j];
            m0 = fmaf(wk, sA[m * 9 + ll],     m0);
            m1 = fmaf(wk, sA[m * 9 + ll + 1], m1);
        }
        sM[j * 9 + ll]     = m0;
        sM[j * 9 + ll + 1] = m1;
    }
    __syncthreads();

    const float cM = 0.125f / 4096.0f;
    {
        float e0 = 0.0f, e1 = 0.0f;
        #pragma unroll 8
        for (int m = 0; m < 64; m++) {
            float wq = sWq[j * 65 + m];
            e0 = fmaf(wq, sM[m * 9 + ll],     e0);
            e1 = fmaf(wq, sM[m * 9 + ll + 1], e1);
        }
        g_Weff[b * 4096 + j * 64 + la]     = fmaf(cM, e0, bw[j * 64 + la]);
        g_Weff[b * 4096 + j * 64 + la + 1] = fmaf(cM, e1, bw[j * 64 + la + 1]);
    }
    if (g == 2 && j < 8) {
        int l = l0 + j;
        float acc = 0.0f;
        #pragma unroll 8
        for (int j2 = 0; j2 < 64; j2++) acc = fmaf(qb[j2], sM[j2 * 9 + j], acc);
        g_beff[b * 64 + l] = fmaf(cM, acc, bb[l]);
    }
}

// ---------------------------------------------------------------------------
// fused layer kernel (grid 272 = 16 producers + 256 consumers, block 256):
// producers: tiny -> W_eff, signal done[layer]. consumers: load ht, spin on
// done, load W, split-K 4x4 GEMM, gelu; mode 0: write g_h + accum S_{layer+1};
// mode 1: fused proj from smem.
// ---------------------------------------------------------------------------
__global__ __launch_bounds__(256) void layer_fused_kernel(
    int layer, int mode,
    const float* __restrict__ qw, const float* __restrict__ qb,
    const float* __restrict__ kw, const float* __restrict__ kb,
    const float* __restrict__ vw, const float* __restrict__ vb,
    const float* __restrict__ bw, const float* __restrict__ bb,
    const float* __restrict__ pw, const float* __restrict__ pb,
    float* __restrict__ out)
{
    extern __shared__ float sm[];
    int tid = threadIdx.x;
    int cta = blockIdx.x;
    unsigned* done = (unsigned*)&g_acc[ACC_DONE + layer];

    if (cta < NPROD) {
        tiny_phase(sm, layer, cta, qw, qb, kw, kb, vw, vb, bw, bb);
        __threadfence();
        __syncthreads();
        if (tid == 0) atomicAdd(done, 1u);
        return;
    }

    // consumer
    float* ht   = sm;                     // [64][HTS]
    float* sw   = ht + 64 * HTS;          // [64][64]
    float* hs   = sw + 64 * 64;           // [32][HSS]
    float* pbuf = hs + TROWS * HSS;       // [32][HSS]

    int r0 = (cta - NPROD) * TROWS;
    int batch = r0 >> 12;

    // prologue independent of W: load h tile transposed
    #pragma unroll
    for (int it = 0; it < 8; it++) {
        int idx = tid + 256 * it;              // 2048 elements
        int r = idx >> 6, j = idx & 63;
        ht[j * HTS + r] = g_h[(r0 + r) * HID + j];
    }

    // wait for producers
    if (tid == 0) {
        unsigned cur;
        do {
            asm volatile("ld.global.acquire.gpu.u32 %0, [%1];"
                         : "=r"(cur) : "l"(done));
            if (cur >= NPROD) break;
            __nanosleep(32);
        } while (true);
    }
    __syncthreads();

    // load W_eff
    #pragma unroll
    for (int it = 0; it < 4; it++) {
        int f = tid + 256 * it;                // 1024 float4s
        *(float4*)(sw + 4 * f) = *(const float4*)(g_Weff + batch * 4096 + 4 * f);
    }
    __syncthreads();

    int wg = tid >> 7;                  // j-half
    int t  = tid & 127;
    int cg = t & 15;                    // cols 4cg..4cg+3
    int rg = t >> 4;                    // rows 4rg..4rg+3
    float acc[4][4];
    #pragma unroll
    for (int a = 0; a < 4; a++)
        #pragma unroll
        for (int b = 0; b < 4; b++) acc[a][b] = 0.0f;

    const float* hp = ht + (32 * wg) * HTS + 4 * rg;
    const float* wp = sw + (32 * wg) * 64 + 4 * cg;
    #pragma unroll 8
    for (int jj = 0; jj < 32; jj++) {
        float4 hv = *(const float4*)(hp + jj * HTS);
        float4 wv = *(const float4*)(wp + jj * 64);
        float ha[4] = {hv.x, hv.y, hv.z, hv.w};
        #pragma unroll
        for (int a = 0; a < 4; a++) {
            acc[a][0] = fmaf(ha[a], wv.x, acc[a][0]);
            acc[a][1] = fmaf(ha[a], wv.y, acc[a][1]);
            acc[a][2] = fmaf(ha[a], wv.z, acc[a][2]);
            acc[a][3] = fmaf(ha[a], wv.w, acc[a][3]);
        }
    }

    int storer = (wg == 0) ? (rg >= 4) : (rg < 4);
    if (storer) {
        #pragma unroll
        for (int a = 0; a < 4; a++)
            *(float4*)(pbuf + (4 * rg + a) * HSS + 4 * cg) =
                make_float4(acc[a][0], acc[a][1], acc[a][2], acc[a][3]);
    }
    __syncthreads();
    if (!storer) {
        float4 be = *(const float4*)(g_beff + batch * 64 + 4 * cg);
        #pragma unroll
        for (int a = 0; a < 4; a++) {
            float4 p = *(const float4*)(pbuf + (4 * rg + a) * HSS + 4 * cg);
            float4 o;
            o.x = gelu_exact(acc[a][0] + p.x + be.x);
            o.y = gelu_exact(acc[a][1] + p.y + be.y);
            o.z = gelu_exact(acc[a][2] + p.z + be.z);
            o.w = gelu_exact(acc[a][3] + p.w + be.w);
            *(float4*)(hs + (4 * rg + a) * HSS + 4 * cg) = o;
        }
    }
    __syncthreads();

    if (mode == 0) {
        #pragma unroll
        for (int it = 0; it < 2; it++) {
            int f = tid + 256 * it;
            int r = f >> 4, j4 = f & 15;
            *(float4*)(g_h + (r0 + r) * HID + 4 * j4) =
                *(const float4*)(hs + r * HSS + 4 * j4);
        }
        accum_S(hs, g_acc + ACC_S + ((layer + 1) * 2 + batch) * (HID * HID),
                g_acc + ACC_SV + ((layer + 1) * 2 + batch) * HID, tid);
    } else {
        int lane = tid & 31, w = tid >> 5;
        #pragma unroll
        for (int k = 0; k < 4; k++) {
            int row = w * 4 + k;
            const float* hr = hs + row * HSS;
            float s = fmaf(hr[lane], pw[lane], hr[lane + 32] * pw[lane + 32]);
            #pragma unroll
            for (int o = 16; o; o >>= 1) s += __shfl_xor_sync(0xffffffffu, s, o);
            if (lane == 0) out[r0 + row] = s + pb[0];
        }
    }
}

// ---------------------------------------------------------------------------
extern "C" void kernel_launch(void* const* d_in, const int* in_sizes, int n_in,
                              void* d_out, int out_size)
{
    const float* x      = (const float*)d_in[0];
    const float* lift_w = (const float*)d_in[1];
    const float* lift_b = (const float*)d_in[2];
    const float* blk_w  = (const float*)d_in[3];
    const float* blk_b  = (const float*)d_in[4];
    const float* q_w    = (const float*)d_in[5];
    const float* q_b    = (const float*)d_in[6];
    const float* k_w    = (const float*)d_in[7];
    const float* k_b    = (const float*)d_in[8];
    const float* v_w    = (const float*)d_in[9];
    const float* v_b    = (const float*)d_in[10];
    const float* proj_w = (const float*)d_in[11];
    const float* proj_b = (const float*)d_in[12];
    float* out = (float*)d_out;

    // dynamic smem = max(tiny 14280, apply 10752) floats
    const int smemF = 14280 * 4;
    static int configured = 0;
    if (!configured) {
        cudaFuncSetAttribute(layer_fused_kernel,
                             cudaFuncAttributeMaxDynamicSharedMemorySize, smemF);
        configured = 1;
    }

    zero_kernel<<<(ACC_TOT + 255) / 256, 256>>>();
    lift_S_kernel<<<NAPPLY, 256>>>(x, lift_w, lift_b);

    for (int i = 0; i < NLAYERS; i++) {
        layer_fused_kernel<<<NAPPLY + NPROD, 256, smemF>>>(
            i, (i == NLAYERS - 1) ? 1 : 0,
            q_w + i * 4096, q_b + i * 64,
            k_w + i * 4096, k_b + i * 64,
            v_w + i * 4096, v_b + i * 64,
            blk_w + i * 4096, blk_b + i * 64,
            proj_w, proj_b, out);
    }
}